// round 8
// baseline (speedup 1.0000x reference)
#include <cuda_runtime.h>
#include <math.h>

// InfoNCE loss: B=131072 rows, D=512 fp32.
// loss = mean_i log(1 + exp((neg_i - pos_i)/T))
// 768 MB streamed once -> pinned near the LTS/HBM ceiling (~7.1 TB/s across
// occ 96/71/44% configs). One warp per row, CTA per 8 rows.
// This round: 256-bit loads (ld.global.nc.v8.f32, sm_100+) -> 6 LDG.256 per
// lane instead of 12 LDG.128: same bytes, half the L1tex wavefront entries.
// Single-node graph (threadfence reduction, no memset).

#define D 512
#define TEMPERATURE 1.5f

__device__ float        g_partial = 0.0f;
__device__ unsigned int g_count   = 0u;

struct f8 { float v[8]; };

__device__ __forceinline__ f8 ldg_nc_256(const void* ptr) {
    f8 r;
    asm volatile("ld.global.nc.v8.f32 {%0,%1,%2,%3,%4,%5,%6,%7}, [%8];"
                 : "=f"(r.v[0]), "=f"(r.v[1]), "=f"(r.v[2]), "=f"(r.v[3]),
                   "=f"(r.v[4]), "=f"(r.v[5]), "=f"(r.v[6]), "=f"(r.v[7])
                 : "l"(ptr));
    return r;
}

__global__ void __launch_bounds__(256, 4)
infonce_kernel(const float* __restrict__ a,
               const float* __restrict__ p,
               const float* __restrict__ n,
               float* __restrict__ out,
               int B, float invB)
{
    const int warp_global = (int)((blockIdx.x * (unsigned)blockDim.x + threadIdx.x) >> 5);
    const int lane = threadIdx.x & 31;

    float aa = 0.f, pp = 0.f, nn = 0.f, ap = 0.f, an = 0.f;

    if (warp_global < B) {
        const size_t row_off = (size_t)warp_global * D;
        const float* __restrict__ ar = a + row_off;
        const float* __restrict__ pr = p + row_off;
        const float* __restrict__ nr = n + row_off;

        // Row = 512 floats = 64 float8 chunks; 32 lanes x 2 iterations.
        // 6 back-to-back LDG.256 per lane, all batched up front.
        f8 va[2], vp[2], vn[2];
        #pragma unroll
        for (int k = 0; k < 2; ++k) va[k] = ldg_nc_256(ar + (lane + 32 * k) * 8);
        #pragma unroll
        for (int k = 0; k < 2; ++k) vp[k] = ldg_nc_256(pr + (lane + 32 * k) * 8);
        #pragma unroll
        for (int k = 0; k < 2; ++k) vn[k] = ldg_nc_256(nr + (lane + 32 * k) * 8);

        #pragma unroll
        for (int k = 0; k < 2; ++k) {
            #pragma unroll
            for (int j = 0; j < 8; ++j) {
                const float x = va[k].v[j];
                const float y = vp[k].v[j];
                const float z = vn[k].v[j];
                aa = fmaf(x, x, aa);
                pp = fmaf(y, y, pp);
                nn = fmaf(z, z, nn);
                ap = fmaf(x, y, ap);
                an = fmaf(x, z, an);
            }
        }
    }

    // Warp tree-reduction of the 5 partial sums.
    #pragma unroll
    for (int off = 16; off > 0; off >>= 1) {
        aa += __shfl_xor_sync(0xFFFFFFFFu, aa, off);
        pp += __shfl_xor_sync(0xFFFFFFFFu, pp, off);
        nn += __shfl_xor_sync(0xFFFFFFFFu, nn, off);
        ap += __shfl_xor_sync(0xFFFFFFFFu, ap, off);
        an += __shfl_xor_sync(0xFFFFFFFFu, an, off);
    }

    float partial = 0.f;
    if (lane == 0 && warp_global < B) {
        const float na  = fmaxf(sqrtf(aa), 1e-12f);
        const float npo = fmaxf(sqrtf(pp), 1e-12f);
        const float nne = fmaxf(sqrtf(nn), 1e-12f);
        const float pos = ap / (na * npo);
        const float neg = an / (na * nne);
        const float z = (neg - pos) * (1.0f / TEMPERATURE);
        // -log_softmax[0] = log(1 + exp(z)); z in [-1.34, 1.34] -> no overflow
        partial = log1pf(expf(z)) * invB;
    }

    // Block reduction (8 warps), then threadfence-reduction across blocks.
    __shared__ float s[8];
    __shared__ bool  is_last;
    const int wid = threadIdx.x >> 5;
    if (lane == 0) s[wid] = partial;
    __syncthreads();
    if (threadIdx.x == 0) {
        float sum = s[0];
        #pragma unroll
        for (int i = 1; i < 8; ++i) sum += s[i];
        atomicAdd(&g_partial, sum);
        __threadfence();
        unsigned int prev = atomicAdd(&g_count, 1u);
        is_last = (prev == gridDim.x - 1u);
        if (is_last) {
            // All other blocks' adds are visible (their fences precede their
            // counter increments). Publish and reset for the next replay.
            *out = g_partial;
            g_partial = 0.0f;
            g_count   = 0u;
        }
    }
}

extern "C" void kernel_launch(void* const* d_in, const int* in_sizes, int n_in,
                              void* d_out, int out_size)
{
    const float* anchors   = (const float*)d_in[0];
    const float* positives = (const float*)d_in[1];
    const float* negatives = (const float*)d_in[2];
    float* out = (float*)d_out;

    const int B = in_sizes[0] / D;

    const int threads = 256;               // 8 warps = 8 rows per block
    const int blocks = (B + 7) / 8;
    infonce_kernel<<<blocks, threads>>>(anchors, positives, negatives, out,
                                        B, 1.0f / (float)B);
}